// round 1
// baseline (speedup 1.0000x reference)
#include <cuda_runtime.h>
#include <cuda_bf16.h>
#include <cstdint>

// Shapes (fixed by the problem): B=4, N=1024, C=64
#define B_ 4
#define N_ 1024
#define C_ 64
#define M_ (B_ * N_)          // 4096 rows for the projections
#define TI 8                  // i-rows per block in the attention kernel

// Scratch for the two projections (device globals: allocation-free rule)
__device__ float g_x1[M_ * C_];
__device__ float g_x2[M_ * C_];

__device__ __forceinline__ float tanh_fast(float x) {
    float y;
    asm("tanh.approx.f32 %0, %1;" : "=f"(y) : "f"(x));
    return y;
}

// ---------------------------------------------------------------------------
// Kernel 1: x1 = x @ W1^T, x2 = x @ W2^T   ([4096,64] x [64,64])
// 256 blocks, each handles 16 rows; W1/W2 staged in shared (padded stride 65
// to kill the stride-64 bank conflict).
// ---------------------------------------------------------------------------
__global__ __launch_bounds__(256) void proj_kernel(
    const float* __restrict__ x,
    const float* __restrict__ W1,
    const float* __restrict__ W2)
{
    __shared__ float W1s[C_ * 65];
    __shared__ float W2s[C_ * 65];
    __shared__ float xs[16 * C_];

    const int tid  = threadIdx.x;
    const int row0 = blockIdx.x * 16;

    for (int k = tid; k < C_ * C_; k += 256) {
        int d = k >> 6, c = k & 63;
        W1s[d * 65 + c] = W1[k];
        W2s[d * 65 + c] = W2[k];
    }
    for (int k = tid; k < 16 * C_; k += 256) {
        xs[k] = x[row0 * C_ + k];
    }
    __syncthreads();

    // 16 rows x 64 outputs = 1024 results; 4 per thread
    #pragma unroll
    for (int rr = 0; rr < 4; ++rr) {
        int idx = rr * 256 + tid;
        int r = idx >> 6;
        int d = idx & 63;
        float a1 = 0.f, a2 = 0.f;
        #pragma unroll
        for (int c = 0; c < C_; ++c) {
            float xv = xs[r * C_ + c];
            a1 = fmaf(xv, W1s[d * 65 + c], a1);
            a2 = fmaf(xv, W2s[d * 65 + c], a2);
        }
        g_x1[(row0 + r) * C_ + d] = a1;
        g_x2[(row0 + r) * C_ + d] = a2;
    }
}

// ---------------------------------------------------------------------------
// Kernel 2: fused att + row-softmax.
// Grid: (N_/TI, B_) blocks of 256 threads. Each block owns TI=8 i-rows of one
// batch. For each j (1 per thread per chunk, 4 chunks): load x2 row (float4),
// accumulate sum_c w3[c]*tanh(x1[i][c] + x2[j][c]) for all 8 i into registers.
// att tile lives in shared (8x1024 = 32KB); softmax done in-block.
// ---------------------------------------------------------------------------
__global__ __launch_bounds__(256) void att_kernel(
    const float* __restrict__ w3,
    float* __restrict__ out)
{
    __shared__ float x1s[TI * C_];
    __shared__ float w3s[C_];
    __shared__ float att_s[TI * N_];   // 32 KB
    __shared__ float red[8];

    const int tid = threadIdx.x;
    const int b   = blockIdx.y;
    const int i0  = blockIdx.x * TI;
    const int lane = tid & 31;
    const int warp = tid >> 5;

    for (int k = tid; k < TI * C_; k += 256)
        x1s[k] = g_x1[(b * N_ + i0) * C_ + k];
    if (tid < C_) w3s[tid] = w3[tid];
    __syncthreads();

    const float* x2b = g_x2 + (size_t)b * N_ * C_;

    #pragma unroll
    for (int chunk = 0; chunk < 4; ++chunk) {
        const int j = chunk * 256 + tid;
        const float4* x2r = reinterpret_cast<const float4*>(x2b + (size_t)j * C_);

        float acc[TI];
        #pragma unroll
        for (int i = 0; i < TI; ++i) acc[i] = 0.f;

        #pragma unroll
        for (int c4 = 0; c4 < C_ / 4; ++c4) {
            const float4 v = x2r[c4];
            const float vv[4] = {v.x, v.y, v.z, v.w};
            #pragma unroll
            for (int u = 0; u < 4; ++u) {
                const int c = c4 * 4 + u;
                const float w = w3s[c];       // broadcast LDS
                const float z = vv[u];
                #pragma unroll
                for (int i = 0; i < TI; ++i) {
                    float t = tanh_fast(x1s[i * C_ + c] + z);  // broadcast LDS
                    acc[i] = fmaf(w, t, acc[i]);
                }
            }
        }
        #pragma unroll
        for (int i = 0; i < TI; ++i)
            att_s[i * N_ + j] = acc[i];
    }
    __syncthreads();

    // ---- softmax over each of the TI rows ----
    for (int i = 0; i < TI; ++i) {
        float* row = att_s + i * N_;

        // block max
        float m = -3.4e38f;
        #pragma unroll
        for (int k = 0; k < 4; ++k) m = fmaxf(m, row[k * 256 + tid]);
        #pragma unroll
        for (int o = 16; o > 0; o >>= 1)
            m = fmaxf(m, __shfl_xor_sync(0xFFFFFFFFu, m, o));
        if (lane == 0) red[warp] = m;
        __syncthreads();
        float bm = red[0];
        #pragma unroll
        for (int w = 1; w < 8; ++w) bm = fmaxf(bm, red[w]);
        __syncthreads();   // red free for reuse

        // exp + block sum (store exp back into the row)
        float s = 0.f;
        #pragma unroll
        for (int k = 0; k < 4; ++k) {
            float e = __expf(row[k * 256 + tid] - bm);
            row[k * 256 + tid] = e;
            s += e;
        }
        #pragma unroll
        for (int o = 16; o > 0; o >>= 1)
            s += __shfl_xor_sync(0xFFFFFFFFu, s, o);
        if (lane == 0) red[warp] = s;
        __syncthreads();
        float bs = red[0];
        #pragma unroll
        for (int w = 1; w < 8; ++w) bs += red[w];
        const float inv = 1.f / bs;

        float* orow = out + ((size_t)(b * N_ + i0 + i)) * N_;
        #pragma unroll
        for (int k = 0; k < 4; ++k)
            orow[k * 256 + tid] = row[k * 256 + tid] * inv;
        __syncthreads();   // red reuse next i
    }
}

extern "C" void kernel_launch(void* const* d_in, const int* in_sizes, int n_in,
                              void* d_out, int out_size)
{
    const float* x  = (const float*)d_in[0];
    const float* W1 = (const float*)d_in[1];
    const float* W2 = (const float*)d_in[2];
    const float* w3 = (const float*)d_in[3];
    float* out = (float*)d_out;

    proj_kernel<<<M_ / 16, 256>>>(x, W1, W2);

    dim3 grid(N_ / TI, B_);
    att_kernel<<<grid, 256>>>(w3, out);
}

// round 2
// speedup vs baseline: 4.1660x; 4.1660x over previous
#include <cuda_runtime.h>
#include <cuda_bf16.h>
#include <cstdint>

// Shapes (fixed by the problem): B=4, N=1024, C=64
#define B_ 4
#define N_ 1024
#define C_ 64
#define M_ (B_ * N_)          // 4096 rows for the projections
#define TI 8                  // i-rows per block in the attention kernel

// Scratch for the two projections (device globals: allocation-free rule)
__device__ float g_x1[M_ * C_];
__device__ float g_x2[M_ * C_];

__device__ __forceinline__ float tanh_fast(float x) {
    float y;
    asm("tanh.approx.f32 %0, %1;" : "=f"(y) : "f"(x));
    return y;
}

// ---------------------------------------------------------------------------
// Kernel 1: x1 = x @ W1^T, x2 = x @ W2^T   ([4096,64] x [64,64])
// ---------------------------------------------------------------------------
__global__ __launch_bounds__(256) void proj_kernel(
    const float* __restrict__ x,
    const float* __restrict__ W1,
    const float* __restrict__ W2)
{
    __shared__ float W1s[C_ * 65];
    __shared__ float W2s[C_ * 65];
    __shared__ float xs[16 * C_];

    const int tid  = threadIdx.x;
    const int row0 = blockIdx.x * 16;

    for (int k = tid; k < C_ * C_; k += 256) {
        int d = k >> 6, c = k & 63;
        W1s[d * 65 + c] = W1[k];
        W2s[d * 65 + c] = W2[k];
    }
    for (int k = tid; k < 16 * C_; k += 256) {
        xs[k] = x[row0 * C_ + k];
    }
    __syncthreads();

    #pragma unroll
    for (int rr = 0; rr < 4; ++rr) {
        int idx = rr * 256 + tid;
        int r = idx >> 6;
        int d = idx & 63;
        float a1 = 0.f, a2 = 0.f;
        #pragma unroll
        for (int c = 0; c < C_; ++c) {
            float xv = xs[r * C_ + c];
            a1 = fmaf(xv, W1s[d * 65 + c], a1);
            a2 = fmaf(xv, W2s[d * 65 + c], a2);
        }
        g_x1[(row0 + r) * C_ + d] = a1;
        g_x2[(row0 + r) * C_ + d] = a2;
    }
}

// ---------------------------------------------------------------------------
// Kernel 2: fused att + row-softmax.
// Grid: (N_/TI, B_), 256 threads. Block owns TI=8 i-rows of one batch.
// Each thread owns 2 j's per chunk (2 chunks of 512 j's). Per c:
//   1 LDS(w3, broadcast) + 8 LDS(x1, broadcast) feed 16 tanh — 3.6 issue
//   slots per tanh, MUFU pipe is the design bottleneck.
// Chunk loop is NOT unrolled; c4 unroll bounded to 4 so at most 8 float4
// of x2 are live -> no spills (R1 lesson).
// ---------------------------------------------------------------------------
__global__ __launch_bounds__(256) void att_kernel(
    const float* __restrict__ w3,
    float* __restrict__ out)
{
    __shared__ float x1s[TI * C_];
    __shared__ float w3s[C_];
    __shared__ float att_s[TI * N_];   // 32 KB
    __shared__ float red[8];

    const int tid = threadIdx.x;
    const int b   = blockIdx.y;
    const int i0  = blockIdx.x * TI;
    const int lane = tid & 31;
    const int warp = tid >> 5;

    for (int k = tid; k < TI * C_; k += 256)
        x1s[k] = g_x1[(b * N_ + i0) * C_ + k];
    if (tid < C_) w3s[tid] = w3[tid];
    __syncthreads();

    const float* x2b = g_x2 + (size_t)b * N_ * C_;

    for (int chunk = 0; chunk < 2; ++chunk) {     // rolled: keeps code small
        const int j0 = chunk * 512 + tid;         // this thread's two j's:
        const int j1 = j0 + 256;                  // j0 and j0+256

        const float4* r0 = reinterpret_cast<const float4*>(x2b + (size_t)j0 * C_);
        const float4* r1 = reinterpret_cast<const float4*>(x2b + (size_t)j1 * C_);

        float acc0[TI], acc1[TI];
        #pragma unroll
        for (int i = 0; i < TI; ++i) { acc0[i] = 0.f; acc1[i] = 0.f; }

        #pragma unroll 4
        for (int c4 = 0; c4 < C_ / 4; ++c4) {
            const float4 v0 = r0[c4];
            const float4 v1 = r1[c4];
            const float a0[4] = {v0.x, v0.y, v0.z, v0.w};
            const float a1[4] = {v1.x, v1.y, v1.z, v1.w};
            #pragma unroll
            for (int u = 0; u < 4; ++u) {
                const int c = c4 * 4 + u;
                const float w  = w3s[c];
                const float z0 = a0[u];
                const float z1 = a1[u];
                #pragma unroll
                for (int i = 0; i < TI; ++i) {
                    const float xv = x1s[i * C_ + c];   // broadcast LDS
                    acc0[i] = fmaf(w, tanh_fast(xv + z0), acc0[i]);
                    acc1[i] = fmaf(w, tanh_fast(xv + z1), acc1[i]);
                }
            }
        }
        #pragma unroll
        for (int i = 0; i < TI; ++i) {
            att_s[i * N_ + j0] = acc0[i];
            att_s[i * N_ + j1] = acc1[i];
        }
    }
    __syncthreads();

    // ---- softmax over each of the TI rows ----
    for (int i = 0; i < TI; ++i) {
        float* row = att_s + i * N_;

        float m = -3.4e38f;
        #pragma unroll
        for (int k = 0; k < 4; ++k) m = fmaxf(m, row[k * 256 + tid]);
        #pragma unroll
        for (int o = 16; o > 0; o >>= 1)
            m = fmaxf(m, __shfl_xor_sync(0xFFFFFFFFu, m, o));
        if (lane == 0) red[warp] = m;
        __syncthreads();
        float bm = red[0];
        #pragma unroll
        for (int w = 1; w < 8; ++w) bm = fmaxf(bm, red[w]);
        __syncthreads();

        float s = 0.f;
        #pragma unroll
        for (int k = 0; k < 4; ++k) {
            float e = __expf(row[k * 256 + tid] - bm);
            row[k * 256 + tid] = e;
            s += e;
        }
        #pragma unroll
        for (int o = 16; o > 0; o >>= 1)
            s += __shfl_xor_sync(0xFFFFFFFFu, s, o);
        if (lane == 0) red[warp] = s;
        __syncthreads();
        float bs = red[0];
        #pragma unroll
        for (int w = 1; w < 8; ++w) bs += red[w];
        const float inv = 1.f / bs;

        float* orow = out + ((size_t)(b * N_ + i0 + i)) * N_;
        #pragma unroll
        for (int k = 0; k < 4; ++k)
            orow[k * 256 + tid] = row[k * 256 + tid] * inv;
        __syncthreads();
    }
}

extern "C" void kernel_launch(void* const* d_in, const int* in_sizes, int n_in,
                              void* d_out, int out_size)
{
    const float* x  = (const float*)d_in[0];
    const float* W1 = (const float*)d_in[1];
    const float* W2 = (const float*)d_in[2];
    const float* w3 = (const float*)d_in[3];
    float* out = (float*)d_out;

    proj_kernel<<<M_ / 16, 256>>>(x, W1, W2);

    dim3 grid(N_ / TI, B_);
    att_kernel<<<grid, 256>>>(w3, out);
}

// round 3
// speedup vs baseline: 4.2856x; 1.0287x over previous
#include <cuda_runtime.h>
#include <cuda_fp16.h>
#include <cstdint>

// Shapes (fixed by the problem): B=4, N=1024, C=64
#define B_ 4
#define N_ 1024
#define C_ 64
#define C2 (C_ / 2)           // 32 half2 per row
#define M_ (B_ * N_)          // 4096 rows
#define TI 8                  // i-rows per att block

// fp16-packed projections (device globals: allocation-free rule)
__device__ __half2 g_x1h[M_ * C2];
__device__ __half2 g_x2h[M_ * C2];

__device__ __forceinline__ __half2 tanh2(__half2 x) {
    unsigned xi = *reinterpret_cast<unsigned*>(&x);
    unsigned yi;
    asm("tanh.approx.f16x2 %0, %1;" : "=r"(yi) : "r"(xi));
    return *reinterpret_cast<__half2*>(&yi);
}

// ---------------------------------------------------------------------------
// Kernel 1: x1 = x @ W1^T, x2 = x @ W2^T, computed fp32, stored half2-packed.
// Each block: 16 rows. Each thread computes 2 (row, d-pair) cells = 4 dots.
// ---------------------------------------------------------------------------
__global__ __launch_bounds__(256) void proj_kernel(
    const float* __restrict__ x,
    const float* __restrict__ W1,
    const float* __restrict__ W2)
{
    __shared__ float W1s[C_ * 65];
    __shared__ float W2s[C_ * 65];
    __shared__ float xs[16 * C_];

    const int tid  = threadIdx.x;
    const int row0 = blockIdx.x * 16;

    for (int k = tid; k < C_ * C_; k += 256) {
        int d = k >> 6, c = k & 63;
        W1s[d * 65 + c] = W1[k];
        W2s[d * 65 + c] = W2[k];
    }
    for (int k = tid; k < 16 * C_; k += 256)
        xs[k] = x[row0 * C_ + k];
    __syncthreads();

    // 16 rows x 32 pairs = 512 pairs; 2 per thread
    #pragma unroll
    for (int pp = 0; pp < 2; ++pp) {
        int idx = pp * 256 + tid;        // pair index 0..511
        int r  = idx >> 5;               // row within tile
        int p  = idx & 31;               // d-pair
        int d0 = 2 * p, d1 = 2 * p + 1;
        float a10 = 0.f, a11 = 0.f, a20 = 0.f, a21 = 0.f;
        #pragma unroll
        for (int c = 0; c < C_; ++c) {
            float xv = xs[r * C_ + c];
            a10 = fmaf(xv, W1s[d0 * 65 + c], a10);
            a11 = fmaf(xv, W1s[d1 * 65 + c], a11);
            a20 = fmaf(xv, W2s[d0 * 65 + c], a20);
            a21 = fmaf(xv, W2s[d1 * 65 + c], a21);
        }
        g_x1h[(row0 + r) * C2 + p] = __floats2half2_rn(a10, a11);
        g_x2h[(row0 + r) * C2 + p] = __floats2half2_rn(a20, a21);
    }
}

// ---------------------------------------------------------------------------
// Kernel 2: fused att + row-softmax, fp16x2 tanh path.
// Grid: (N_/TI, B_) = 512 blocks of 256 threads -> single wave at 4 blk/SM.
// Thread owns 4 j's (one per chunk). Per j: 4 groups of 8 c-pairs; half2
// accumulators per i, flushed to fp32 after each group (precision).
// MUFU does 2 tanh per op -> 32 tanh-lanes/cyc/SM design ceiling.
// ---------------------------------------------------------------------------
__global__ __launch_bounds__(256) void att_kernel(
    const float* __restrict__ w3,
    float* __restrict__ out)
{
    __shared__ __half2 x1s[TI * C2];     // 1 KB
    __shared__ __half2 w3s[C2];          // 128 B
    __shared__ float att_s[TI * N_];     // 32 KB
    __shared__ float red[8];

    const int tid  = threadIdx.x;
    const int b    = blockIdx.y;
    const int i0   = blockIdx.x * TI;
    const int lane = tid & 31;
    const int warp = tid >> 5;

    if (tid < TI * C2)
        x1s[tid] = g_x1h[(b * N_ + i0) * C2 + tid];
    if (tid < C2)
        w3s[tid] = __floats2half2_rn(w3[2 * tid], w3[2 * tid + 1]);
    __syncthreads();

    const __half2* x2b = g_x2h + (size_t)b * N_ * C2;

    for (int chunk = 0; chunk < 4; ++chunk) {      // rolled
        const int j = chunk * 256 + tid;
        const __half2* x2r = x2b + (size_t)j * C2;

        float acc[TI];
        #pragma unroll
        for (int i = 0; i < TI; ++i) acc[i] = 0.f;

        for (int g = 0; g < 4; ++g) {              // rolled: bounds live regs
            // load this group's 8 x2 half2 (32 B) via two 16B loads
            __half2 v[8];
            {
                const uint4* p = reinterpret_cast<const uint4*>(x2r + g * 8);
                uint4 q0 = p[0], q1 = p[1];
                unsigned* vv = reinterpret_cast<unsigned*>(v);
                vv[0] = q0.x; vv[1] = q0.y; vv[2] = q0.z; vv[3] = q0.w;
                vv[4] = q1.x; vv[5] = q1.y; vv[6] = q1.z; vv[7] = q1.w;
            }

            __half2 accH[TI];
            #pragma unroll
            for (int i = 0; i < TI; ++i)
                accH[i] = __floats2half2_rn(0.f, 0.f);

            #pragma unroll
            for (int k = 0; k < 8; ++k) {
                const int cp = g * 8 + k;
                const __half2 w = w3s[cp];          // broadcast LDS
                const __half2 z = v[k];
                #pragma unroll
                for (int i = 0; i < TI; ++i) {
                    __half2 s = __hadd2(x1s[i * C2 + cp], z);  // broadcast LDS
                    accH[i] = __hfma2(w, tanh2(s), accH[i]);
                }
            }
            #pragma unroll
            for (int i = 0; i < TI; ++i) {
                float2 f = __half22float2(accH[i]);
                acc[i] += f.x + f.y;
            }
        }
        #pragma unroll
        for (int i = 0; i < TI; ++i)
            att_s[i * N_ + j] = acc[i];
    }
    __syncthreads();

    // ---- softmax over each of the TI rows ----
    for (int i = 0; i < TI; ++i) {
        float* row = att_s + i * N_;

        float m = -3.4e38f;
        #pragma unroll
        for (int k = 0; k < 4; ++k) m = fmaxf(m, row[k * 256 + tid]);
        #pragma unroll
        for (int o = 16; o > 0; o >>= 1)
            m = fmaxf(m, __shfl_xor_sync(0xFFFFFFFFu, m, o));
        if (lane == 0) red[warp] = m;
        __syncthreads();
        float bm = red[0];
        #pragma unroll
        for (int w = 1; w < 8; ++w) bm = fmaxf(bm, red[w]);
        __syncthreads();

        float s = 0.f;
        #pragma unroll
        for (int k = 0; k < 4; ++k) {
            float e = __expf(row[k * 256 + tid] - bm);
            row[k * 256 + tid] = e;
            s += e;
        }
        #pragma unroll
        for (int o = 16; o > 0; o >>= 1)
            s += __shfl_xor_sync(0xFFFFFFFFu, s, o);
        if (lane == 0) red[warp] = s;
        __syncthreads();
        float bs = red[0];
        #pragma unroll
        for (int w = 1; w < 8; ++w) bs += red[w];
        const float inv = 1.f / bs;

        float* orow = out + ((size_t)(b * N_ + i0 + i)) * N_;
        #pragma unroll
        for (int k = 0; k < 4; ++k)
            orow[k * 256 + tid] = row[k * 256 + tid] * inv;
        __syncthreads();
    }
}

extern "C" void kernel_launch(void* const* d_in, const int* in_sizes, int n_in,
                              void* d_out, int out_size)
{
    const float* x  = (const float*)d_in[0];
    const float* W1 = (const float*)d_in[1];
    const float* W2 = (const float*)d_in[2];
    const float* w3 = (const float*)d_in[3];
    float* out = (float*)d_out;

    proj_kernel<<<M_ / 16, 256>>>(x, W1, W2);

    dim3 grid(N_ / TI, B_);
    att_kernel<<<grid, 256>>>(w3, out);
}